// round 4
// baseline (speedup 1.0000x reference)
#include <cuda_runtime.h>

// ---------------------------------------------------------------------------
// Sparse masked 3D U-Net (presetUResNet) on 96^3 grid, fp32.
// R3: channel-group layout feat[c/4][v][4]; float4 input gathers with good
// line locality; CO_TILE=8 register tile; interior fast path; no arena zeroing
// (static zero-init + idempotent writes); fused prep so launch #6 = main conv.
// ---------------------------------------------------------------------------

constexpr int D0 = 96, D1 = 48, D2 = 24;
constexpr int V0 = D0 * D0 * D0;   // 884736
constexpr int V1 = D1 * D1 * D1;   // 110592
constexpr int V2 = D2 * D2 * D2;   // 13824

// ---- scratch arena (floats); feature buffers in [c/4][v][4] layout ----
constexpr int OFF_XM    = 0;                    // 1  * V0 (masked input, scalar)
constexpr int OFF_SKIP0 = OFF_XM    + V0;       // 16 * V0
constexpr int OFF_UP1   = OFF_SKIP0 + 16 * V0;  // 16 * V0
constexpr int OFF_T32   = OFF_UP1   + 16 * V0;  // 32 * V0
constexpr int OFF_HA    = OFF_T32   + 32 * V0;  // 32 * V1
constexpr int OFF_HB    = OFF_HA    + 32 * V1;  // 32 * V1
constexpr int OFF_S1    = OFF_HB    + 32 * V1;  // 32 * V1
constexpr int OFF_H64   = OFF_S1    + 32 * V1;  // 64 * V1
constexpr int OFF_CA    = OFF_H64   + 64 * V1;  // 64 * V2
constexpr int OFF_CB    = OFF_CA    + 64 * V2;  // 64 * V2
constexpr int FEAT_END  = OFF_CB    + 64 * V2;
constexpr int OFF_M1    = FEAT_END;             // V1 mask
constexpr int OFF_M2    = OFF_M1 + V1;          // V2 mask
constexpr int OFF_W     = OFF_M2 + V2;
// transposed weights: layout [(t*Cin + ci)*Copad + o]
constexpr int WO_IN  = OFF_W;
constexpr int WO_E0D = WO_IN  + 1  * 27 * 16;
constexpr int WO_E0A = WO_E0D + 16 * 8  * 32;
constexpr int WO_E0B = WO_E0A + 32 * 27 * 32;
constexpr int WO_E1D = WO_E0B + 32 * 27 * 32;
constexpr int WO_E1A = WO_E1D + 32 * 8  * 64;
constexpr int WO_E1B = WO_E1A + 64 * 27 * 64;
constexpr int WO_D0U = WO_E1B + 64 * 27 * 64;
constexpr int WO_D0A = WO_D0U + 64 * 8  * 32;
constexpr int WO_D0B = WO_D0A + 64 * 27 * 64;
constexpr int WO_D1U = WO_D0B + 64 * 27 * 32;
constexpr int WO_D1A = WO_D1U + 32 * 8  * 16;
constexpr int WO_D1B = WO_D1A + 32 * 27 * 32;
constexpr int WO_OA  = WO_D1B + 32 * 27 * 16;
constexpr int WO_OB  = WO_OA  + 16 * 27 * 16;
constexpr int SCRATCH_TOTAL = WO_OB + 16 * 27 * 8;

__device__ __align__(256) float g_scratch[SCRATCH_TOTAL];  // zero-initialized
__device__ int g_list0[V0];
__device__ int g_list1[V1];
__device__ int g_list2[V2];
__device__ int g_cnt[4];

// ---------------------------------------------------------------------------
// prep kernels (fused so the first big conv3 lands at launch index 5)
// ---------------------------------------------------------------------------

// zero d_out, masked input xm, masks m1/m2 (direct 2^3 / 4^3 max of occ), cnt
__global__ void prep1_kernel(const float* __restrict__ x,
                             const float* __restrict__ occ,
                             float* __restrict__ out, int outn) {
    int stride = gridDim.x * blockDim.x;
    int gt = blockIdx.x * blockDim.x + threadIdx.x;
    float4 z4 = make_float4(0.f, 0.f, 0.f, 0.f);
    float4* o4 = reinterpret_cast<float4*>(out);
    for (int i = gt; i < outn / 4; i += stride) o4[i] = z4;
    for (int i = gt; i < V0; i += stride) g_scratch[OFF_XM + i] = x[i] * occ[i];
    for (int i = gt; i < V1; i += stride) {
        int xx = i % D1, yy = (i / D1) % D1, zz = i / (D1 * D1);
        float m = 0.f;
        #pragma unroll
        for (int dz = 0; dz < 2; dz++)
            #pragma unroll
            for (int dy = 0; dy < 2; dy++)
                #pragma unroll
                for (int dx = 0; dx < 2; dx++)
                    m = fmaxf(m, occ[((2 * zz + dz) * D0 + 2 * yy + dy) * D0 + 2 * xx + dx]);
        g_scratch[OFF_M1 + i] = m;
    }
    for (int i = gt; i < V2; i += stride) {
        int xx = i % D2, yy = (i / D2) % D2, zz = i / (D2 * D2);
        float m = 0.f;
        for (int dz = 0; dz < 4; dz++)
            for (int dy = 0; dy < 4; dy++)
                #pragma unroll
                for (int dx = 0; dx < 4; dx++)
                    m = fmaxf(m, occ[((4 * zz + dz) * D0 + 4 * yy + dy) * D0 + 4 * xx + dx]);
        g_scratch[OFF_M2 + i] = m;
    }
    if (gt == 0) { g_cnt[0] = 0; g_cnt[1] = 0; g_cnt[2] = 0; g_cnt[3] = 0; }
}

// build all 3 occupancy lists (blockIdx.y selects level)
__global__ void lists_kernel(const float* __restrict__ occ) {
    const float* mask; int n; int* list; int* cnt;
    if (blockIdx.y == 0)      { mask = occ;                 n = V0; list = g_list0; cnt = &g_cnt[0]; }
    else if (blockIdx.y == 1) { mask = g_scratch + OFF_M1;  n = V1; list = g_list1; cnt = &g_cnt[1]; }
    else                      { mask = g_scratch + OFF_M2;  n = V2; list = g_list2; cnt = &g_cnt[2]; }
    int lane = threadIdx.x & 31;
    for (int i = blockIdx.x * blockDim.x + threadIdx.x; i < n + 31;
         i += gridDim.x * blockDim.x) {
        bool pred = (i < n) && (mask[i] > 0.5f);
        unsigned bal = __ballot_sync(0xffffffffu, pred);
        int leader = __ffs(bal) - 1;
        int base = 0;
        if (bal && lane == leader) base = atomicAdd(cnt, __popc(bal));
        base = __shfl_sync(0xffffffffu, base, leader < 0 ? 0 : leader);
        if (pred) list[base + __popc(bal & ((1u << lane) - 1))] = i;
    }
}

// all 15 weight transposes in one launch (blockIdx.y = weight index)
struct WPtrs { const float* p[15]; };
__device__ const int TW_DIMS[15][4] = {
    {16, 1, 27, 16}, {32, 16, 8, 32}, {32, 32, 27, 32}, {32, 32, 27, 32},
    {64, 32, 8, 64}, {64, 64, 27, 64}, {64, 64, 27, 64}, {32, 64, 8, 32},
    {64, 64, 27, 64}, {32, 64, 27, 32}, {16, 32, 8, 16}, {32, 32, 27, 32},
    {16, 32, 27, 16}, {16, 16, 27, 16}, {5, 16, 27, 8}};
__device__ const int TW_OFF[15] = {
    WO_IN, WO_E0D, WO_E0A, WO_E0B, WO_E1D, WO_E1A, WO_E1B, WO_D0U,
    WO_D0A, WO_D0B, WO_D1U, WO_D1A, WO_D1B, WO_OA, WO_OB};

__global__ void tw_kernel(WPtrs wp) {
    int e = blockIdx.y;
    int Cout = TW_DIMS[e][0], Cin = TW_DIMS[e][1], K3 = TW_DIMS[e][2], Copad = TW_DIMS[e][3];
    const float* w = wp.p[e];
    float* wt = g_scratch + TW_OFF[e];
    int total = Cin * K3 * Copad;
    for (int i = blockIdx.x * blockDim.x + threadIdx.x; i < total;
         i += gridDim.x * blockDim.x) {
        int o = i % Copad;
        int r = i / Copad;
        int t = r / Cin, ci = r % Cin;
        wt[i] = (o < Cout) ? w[(o * Cin + ci) * K3 + t] : 0.f;
    }
}

// ---------------------------------------------------------------------------
// conv inner helpers (channel-group layout)
// ---------------------------------------------------------------------------

template <int COPAD, int CO_TILE>
__device__ __forceinline__ void fmas(float* acc, float4 iv, const float* __restrict__ wp) {
    float f[4] = {iv.x, iv.y, iv.z, iv.w};
    #pragma unroll
    for (int j = 0; j < 4; j++) {
        #pragma unroll
        for (int c = 0; c < CO_TILE; c += 4) {
            float4 wv = __ldg(reinterpret_cast<const float4*>(wp + j * COPAD + c));
            acc[c + 0] += f[j] * wv.x; acc[c + 1] += f[j] * wv.y;
            acc[c + 2] += f[j] * wv.z; acc[c + 3] += f[j] * wv.w;
        }
    }
}

template <int ICGA, int ICGB, int COPAD, int CO_TILE>
__device__ __forceinline__ void tap_accum(float* acc, const float* __restrict__ inA,
                                          const float* __restrict__ inB,
                                          const float* __restrict__ wtap,
                                          int noff, int vol, int co_base) {
    #pragma unroll 4
    for (int g = 0; g < ICGA; g++) {
        float4 iv = __ldg(reinterpret_cast<const float4*>(inA + ((long)g * vol + noff) * 4));
        fmas<COPAD, CO_TILE>(acc, iv, wtap + g * 4 * COPAD + co_base);
    }
    #pragma unroll 4
    for (int g = 0; g < ICGB; g++) {
        float4 iv = __ldg(reinterpret_cast<const float4*>(inB + ((long)g * vol + noff) * 4));
        fmas<COPAD, CO_TILE>(acc, iv, wtap + (ICGA + g) * 4 * COPAD + co_base);
    }
}

// ---------------------------------------------------------------------------
// gather convs
// ---------------------------------------------------------------------------

template <int ICGA, int ICGB, int OCG, int CO_TILE, bool RELU>
__global__ __launch_bounds__(256)
void conv3_vec(const float* __restrict__ inA, const float* __restrict__ inB,
               const float* __restrict__ wt, float* __restrict__ out,
               const int* __restrict__ list, const int* __restrict__ cnt,
               int cntIdx, int D) {
    constexpr int ICGT = ICGA + ICGB;
    constexpr int COPAD = OCG * 4;
    constexpr int TPV = COPAD / CO_TILE;
    const int vol = D * D * D;
    const int WSTRIDE = ICGT * 4 * COPAD;
    int n = cnt[cntIdx];
    int total = n * TPV;
    for (int w = blockIdx.x * blockDim.x + threadIdx.x; w < total;
         w += gridDim.x * blockDim.x) {
        int v = list[w / TPV];
        int co_base = (w % TPV) * CO_TILE;
        int x0 = v % D, y0 = (v / D) % D, z0 = v / (D * D);
        float acc[CO_TILE];
        #pragma unroll
        for (int k = 0; k < CO_TILE; k++) acc[k] = 0.f;
        if (x0 >= 1 && x0 < D - 1 && y0 >= 1 && y0 < D - 1 && z0 >= 1 && z0 < D - 1) {
            const float* wtap = wt;
            #pragma unroll 1
            for (int dz = -1; dz <= 1; dz++) {
                #pragma unroll 1
                for (int dy = -1; dy <= 1; dy++) {
                    int base = v + (dz * D + dy) * D;
                    #pragma unroll
                    for (int dx = -1; dx <= 1; dx++) {
                        tap_accum<ICGA, ICGB, COPAD, CO_TILE>(
                            acc, inA, inB, wtap, base + dx, vol, co_base);
                        wtap += WSTRIDE;
                    }
                }
            }
        } else {
            #pragma unroll 1
            for (int dz = -1; dz <= 1; dz++) {
                int zz = z0 + dz;
                if ((unsigned)zz >= (unsigned)D) continue;
                #pragma unroll 1
                for (int dy = -1; dy <= 1; dy++) {
                    int yy = y0 + dy;
                    if ((unsigned)yy >= (unsigned)D) continue;
                    #pragma unroll 1
                    for (int dx = -1; dx <= 1; dx++) {
                        int xx = x0 + dx;
                        if ((unsigned)xx >= (unsigned)D) continue;
                        int t = ((dz + 1) * 3 + dy + 1) * 3 + dx + 1;
                        int noff = (zz * D + yy) * D + xx;
                        tap_accum<ICGA, ICGB, COPAD, CO_TILE>(
                            acc, inA, inB, wt + t * WSTRIDE, noff, vol, co_base);
                    }
                }
            }
        }
        if (RELU) {
            #pragma unroll
            for (int k = 0; k < CO_TILE; k++) acc[k] = fmaxf(acc[k], 0.f);
        }
        int ocg0 = co_base / 4;
        #pragma unroll
        for (int k = 0; k < CO_TILE; k += 4)
            *reinterpret_cast<float4*>(out + ((long)(ocg0 + k / 4) * vol + v) * 4) =
                make_float4(acc[k], acc[k + 1], acc[k + 2], acc[k + 3]);
    }
}

// dedicated input conv: 1 -> 16 channels @ 96^3
__global__ __launch_bounds__(256)
void conv_in_vec(const float* __restrict__ xm, const float* __restrict__ wt,
                 float* __restrict__ out, const int* __restrict__ list,
                 const int* __restrict__ cnt) {
    const int D = D0, vol = V0;
    int n = cnt[0];
    for (int w = blockIdx.x * blockDim.x + threadIdx.x; w < n;
         w += gridDim.x * blockDim.x) {
        int v = list[w];
        int x0 = v % D, y0 = (v / D) % D, z0 = v / (D * D);
        float acc[16];
        #pragma unroll
        for (int k = 0; k < 16; k++) acc[k] = 0.f;
        #pragma unroll 1
        for (int dz = -1; dz <= 1; dz++) {
            int zz = z0 + dz;
            if ((unsigned)zz >= (unsigned)D) continue;
            #pragma unroll 1
            for (int dy = -1; dy <= 1; dy++) {
                int yy = y0 + dy;
                if ((unsigned)yy >= (unsigned)D) continue;
                #pragma unroll
                for (int dx = -1; dx <= 1; dx++) {
                    int xx = x0 + dx;
                    if ((unsigned)xx >= (unsigned)D) continue;
                    int t = ((dz + 1) * 3 + dy + 1) * 3 + dx + 1;
                    float iv = __ldg(xm + (zz * D + yy) * D + xx);
                    const float* wp = wt + t * 16;
                    #pragma unroll
                    for (int c = 0; c < 16; c += 4) {
                        float4 wv = __ldg(reinterpret_cast<const float4*>(wp + c));
                        acc[c + 0] += iv * wv.x; acc[c + 1] += iv * wv.y;
                        acc[c + 2] += iv * wv.z; acc[c + 3] += iv * wv.w;
                    }
                }
            }
        }
        #pragma unroll
        for (int k = 0; k < 16; k += 4)
            *reinterpret_cast<float4*>(out + ((long)(k / 4) * vol + v) * 4) =
                make_float4(acc[k], acc[k + 1], acc[k + 2], acc[k + 3]);
    }
}

// dedicated output conv: 16 -> 5 channels, dense NCDHW output
__global__ __launch_bounds__(256)
void conv_out_vec(const float* __restrict__ in, const float* __restrict__ wt,
                  float* __restrict__ out, const int* __restrict__ list,
                  const int* __restrict__ cnt) {
    const int D = D0, vol = V0;
    int n = cnt[0];
    for (int w = blockIdx.x * blockDim.x + threadIdx.x; w < n;
         w += gridDim.x * blockDim.x) {
        int v = list[w];
        int x0 = v % D, y0 = (v / D) % D, z0 = v / (D * D);
        float acc[8];
        #pragma unroll
        for (int k = 0; k < 8; k++) acc[k] = 0.f;
        #pragma unroll 1
        for (int dz = -1; dz <= 1; dz++) {
            int zz = z0 + dz;
            if ((unsigned)zz >= (unsigned)D) continue;
            #pragma unroll 1
            for (int dy = -1; dy <= 1; dy++) {
                int yy = y0 + dy;
                if ((unsigned)yy >= (unsigned)D) continue;
                #pragma unroll 1
                for (int dx = -1; dx <= 1; dx++) {
                    int xx = x0 + dx;
                    if ((unsigned)xx >= (unsigned)D) continue;
                    int t = ((dz + 1) * 3 + dy + 1) * 3 + dx + 1;
                    int noff = (zz * D + yy) * D + xx;
                    tap_accum<4, 0, 8, 8>(acc, in, nullptr, wt + t * 16 * 8, noff, vol, 0);
                }
            }
        }
        #pragma unroll
        for (int c = 0; c < 5; c++) out[(long)c * vol + v] = acc[c];
    }
}

template <int ICG, int OCG, int CO_TILE>
__global__ __launch_bounds__(256)
void down2_vec(const float* __restrict__ in, const float* __restrict__ wt,
               float* __restrict__ out, const int* __restrict__ list,
               const int* __restrict__ cnt, int cntIdx, int Dc) {
    constexpr int COPAD = OCG * 4;
    constexpr int TPV = COPAD / CO_TILE;
    const int Df = Dc * 2;
    const int volf = Df * Df * Df;
    const int volc = Dc * Dc * Dc;
    int n = cnt[cntIdx];
    int total = n * TPV;
    for (int w = blockIdx.x * blockDim.x + threadIdx.x; w < total;
         w += gridDim.x * blockDim.x) {
        int v = list[w / TPV];
        int co_base = (w % TPV) * CO_TILE;
        int x0 = v % Dc, y0 = (v / Dc) % Dc, z0 = v / (Dc * Dc);
        float acc[CO_TILE];
        #pragma unroll
        for (int k = 0; k < CO_TILE; k++) acc[k] = 0.f;
        #pragma unroll 1
        for (int t = 0; t < 8; t++) {
            int tz = t >> 2, ty = (t >> 1) & 1, tx = t & 1;
            int noff = ((2 * z0 + tz) * Df + 2 * y0 + ty) * Df + 2 * x0 + tx;
            tap_accum<ICG, 0, COPAD, CO_TILE>(acc, in, nullptr,
                                              wt + t * ICG * 4 * COPAD, noff, volf, co_base);
        }
        int ocg0 = co_base / 4;
        #pragma unroll
        for (int k = 0; k < CO_TILE; k += 4)
            *reinterpret_cast<float4*>(out + ((long)(ocg0 + k / 4) * volc + v) * 4) =
                make_float4(acc[k], acc[k + 1], acc[k + 2], acc[k + 3]);
    }
}

template <int ICG, int OCG, int CO_TILE>
__global__ __launch_bounds__(256)
void up2_vec(const float* __restrict__ in, const float* __restrict__ wt,
             float* __restrict__ out, const int* __restrict__ list,
             const int* __restrict__ cnt, int cntIdx, int Df) {
    constexpr int COPAD = OCG * 4;
    constexpr int TPV = COPAD / CO_TILE;
    const int Dc = Df / 2;
    const int volf = Df * Df * Df;
    const int volc = Dc * Dc * Dc;
    int n = cnt[cntIdx];
    int total = n * TPV;
    for (int w = blockIdx.x * blockDim.x + threadIdx.x; w < total;
         w += gridDim.x * blockDim.x) {
        int v = list[w / TPV];
        int co_base = (w % TPV) * CO_TILE;
        int x0 = v % Df, y0 = (v / Df) % Df, z0 = v / (Df * Df);
        int t = ((1 - (z0 & 1)) * 2 + (1 - (y0 & 1))) * 2 + (1 - (x0 & 1));
        int coff = ((z0 >> 1) * Dc + (y0 >> 1)) * Dc + (x0 >> 1);
        float acc[CO_TILE];
        #pragma unroll
        for (int k = 0; k < CO_TILE; k++) acc[k] = 0.f;
        tap_accum<ICG, 0, COPAD, CO_TILE>(acc, in, nullptr,
                                          wt + t * ICG * 4 * COPAD, coff, volc, co_base);
        int ocg0 = co_base / 4;
        #pragma unroll
        for (int k = 0; k < CO_TILE; k += 4)
            *reinterpret_cast<float4*>(out + ((long)(ocg0 + k / 4) * volf + v) * 4) =
                make_float4(acc[k], acc[k + 1], acc[k + 2], acc[k + 3]);
    }
}

// ---------------------------------------------------------------------------
// launch
// ---------------------------------------------------------------------------

static inline int nblk(long total) {
    long b = (total + 255) / 256;
    return (int)(b < 2048 ? b : 2048);
}

extern "C" void kernel_launch(void* const* d_in, const int* in_sizes, int n_in,
                              void* d_out, int out_size) {
    (void)in_sizes; (void)n_in;
    const float* x   = (const float*)d_in[0];
    const float* occ = (const float*)d_in[1];
    float* out = (float*)d_out;

    float* SB = nullptr;
    int *L0 = nullptr, *L1 = nullptr, *L2 = nullptr, *CNT = nullptr;
    cudaGetSymbolAddress((void**)&SB,  g_scratch);
    cudaGetSymbolAddress((void**)&L0,  g_list0);
    cudaGetSymbolAddress((void**)&L1,  g_list1);
    cudaGetSymbolAddress((void**)&L2,  g_list2);
    cudaGetSymbolAddress((void**)&CNT, g_cnt);

    // launch 0: out zero + xm + m1 + m2 + cnt reset
    prep1_kernel<<<1024, 256>>>(x, occ, out, out_size);
    // launch 1: all 3 occupancy lists
    lists_kernel<<<dim3(432, 3), 256>>>(occ);
    // launch 2: all weight transposes
    WPtrs wp;
    for (int i = 0; i < 15; i++) wp.p[i] = (const float*)d_in[2 + i];
    tw_kernel<<<dim3(216, 15), 256>>>(wp);

    // launch 3: input conv 1->16 @96
    conv_in_vec<<<nblk(V0), 256>>>(SB + OFF_XM, SB + WO_IN, SB + OFF_SKIP0, L0, CNT);

    // encoder level 0
    down2_vec<4, 8, 8><<<nblk((long)V1 * 4), 256>>>(
        SB + OFF_SKIP0, SB + WO_E0D, SB + OFF_HA, L1, CNT, 1, D1);
    // launch 5 (profiled): 32->32 conv3 @48
    conv3_vec<8, 0, 8, 8, true><<<nblk((long)V1 * 4), 256>>>(
        SB + OFF_HA, nullptr, SB + WO_E0A, SB + OFF_HB, L1, CNT, 1, D1);
    conv3_vec<8, 0, 8, 8, false><<<nblk((long)V1 * 4), 256>>>(
        SB + OFF_HB, nullptr, SB + WO_E0B, SB + OFF_S1, L1, CNT, 1, D1);

    // encoder level 1
    down2_vec<8, 16, 8><<<nblk((long)V2 * 8), 256>>>(
        SB + OFF_S1, SB + WO_E1D, SB + OFF_CA, L2, CNT, 2, D2);
    conv3_vec<16, 0, 16, 8, true><<<nblk((long)V2 * 8), 256>>>(
        SB + OFF_CA, nullptr, SB + WO_E1A, SB + OFF_CB, L2, CNT, 2, D2);
    conv3_vec<16, 0, 16, 8, false><<<nblk((long)V2 * 8), 256>>>(
        SB + OFF_CB, nullptr, SB + WO_E1B, SB + OFF_CA, L2, CNT, 2, D2);

    // decoder stage 0 (to level 1)
    up2_vec<16, 8, 8><<<nblk((long)V1 * 4), 256>>>(
        SB + OFF_CA, SB + WO_D0U, SB + OFF_HA, L1, CNT, 1, D1);
    conv3_vec<8, 8, 16, 8, true><<<nblk((long)V1 * 8), 256>>>(
        SB + OFF_HA, SB + OFF_S1, SB + WO_D0A, SB + OFF_H64, L1, CNT, 1, D1);
    conv3_vec<16, 0, 8, 8, false><<<nblk((long)V1 * 4), 256>>>(
        SB + OFF_H64, nullptr, SB + WO_D0B, SB + OFF_HB, L1, CNT, 1, D1);

    // decoder stage 1 (to level 0)
    up2_vec<8, 4, 8><<<nblk((long)V0 * 2), 256>>>(
        SB + OFF_HB, SB + WO_D1U, SB + OFF_UP1, L0, CNT, 0, D0);
    conv3_vec<4, 4, 8, 8, true><<<nblk((long)V0 * 4), 256>>>(
        SB + OFF_UP1, SB + OFF_SKIP0, SB + WO_D1A, SB + OFF_T32, L0, CNT, 0, D0);
    conv3_vec<8, 0, 4, 8, false><<<nblk((long)V0 * 2), 256>>>(
        SB + OFF_T32, nullptr, SB + WO_D1B, SB + OFF_UP1, L0, CNT, 0, D0);

    // output block
    conv3_vec<4, 0, 4, 8, true><<<nblk((long)V0 * 2), 256>>>(
        SB + OFF_UP1, nullptr, SB + WO_OA, SB + OFF_SKIP0, L0, CNT, 0, D0);
    conv_out_vec<<<nblk(V0), 256>>>(SB + OFF_SKIP0, SB + WO_OB, out, L0, CNT);
}

// round 5
// speedup vs baseline: 1.1886x; 1.1886x over previous
#include <cuda_runtime.h>

// ---------------------------------------------------------------------------
// Sparse masked 3D U-Net (presetUResNet) on 96^3 grid, fp32.
// R4: latency-oriented conv3: 9-deep batched float4 input gathers (MLP=9),
// weights staged per ci-group in shared memory, CO_TILE=4 for occupancy.
// Feature layout [c/4][v][4] (channel groups of 4, float4 per voxel).
// ---------------------------------------------------------------------------

constexpr int D0 = 96, D1 = 48, D2 = 24;
constexpr int V0 = D0 * D0 * D0;
constexpr int V1 = D1 * D1 * D1;
constexpr int V2 = D2 * D2 * D2;

// ---- scratch arena (floats) ----
constexpr int OFF_XM    = 0;
constexpr int OFF_SKIP0 = OFF_XM    + V0;
constexpr int OFF_UP1   = OFF_SKIP0 + 16 * V0;
constexpr int OFF_T32   = OFF_UP1   + 16 * V0;
constexpr int OFF_HA    = OFF_T32   + 32 * V0;
constexpr int OFF_HB    = OFF_HA    + 32 * V1;
constexpr int OFF_S1    = OFF_HB    + 32 * V1;
constexpr int OFF_H64   = OFF_S1    + 32 * V1;
constexpr int OFF_CA    = OFF_H64   + 64 * V1;
constexpr int OFF_CB    = OFF_CA    + 64 * V2;
constexpr int FEAT_END  = OFF_CB    + 64 * V2;
constexpr int OFF_M1    = FEAT_END;
constexpr int OFF_M2    = OFF_M1 + V1;
constexpr int OFF_W     = OFF_M2 + V2;
// transposed weights: [(t*Cin + ci)*Copad + o]
constexpr int WO_IN  = OFF_W;
constexpr int WO_E0D = WO_IN  + 1  * 27 * 16;
constexpr int WO_E0A = WO_E0D + 16 * 8  * 32;
constexpr int WO_E0B = WO_E0A + 32 * 27 * 32;
constexpr int WO_E1D = WO_E0B + 32 * 27 * 32;
constexpr int WO_E1A = WO_E1D + 32 * 8  * 64;
constexpr int WO_E1B = WO_E1A + 64 * 27 * 64;
constexpr int WO_D0U = WO_E1B + 64 * 27 * 64;
constexpr int WO_D0A = WO_D0U + 64 * 8  * 32;
constexpr int WO_D0B = WO_D0A + 64 * 27 * 64;
constexpr int WO_D1U = WO_D0B + 64 * 27 * 32;
constexpr int WO_D1A = WO_D1U + 32 * 8  * 16;
constexpr int WO_D1B = WO_D1A + 32 * 27 * 32;
constexpr int WO_OA  = WO_D1B + 32 * 27 * 16;
constexpr int WO_OB  = WO_OA  + 16 * 27 * 16;
constexpr int SCRATCH_TOTAL = WO_OB + 16 * 27 * 8;

__device__ __align__(256) float g_scratch[SCRATCH_TOTAL];  // zero-initialized
__device__ int g_list0[V0];
__device__ int g_list1[V1];
__device__ int g_list2[V2];
__device__ int g_cnt[4];

// ---------------------------------------------------------------------------
// prep kernels
// ---------------------------------------------------------------------------

__global__ void prep1_kernel(const float* __restrict__ x,
                             const float* __restrict__ occ,
                             float* __restrict__ out, int outn) {
    int stride = gridDim.x * blockDim.x;
    int gt = blockIdx.x * blockDim.x + threadIdx.x;
    float4 z4 = make_float4(0.f, 0.f, 0.f, 0.f);
    float4* o4 = reinterpret_cast<float4*>(out);
    for (int i = gt; i < outn / 4; i += stride) o4[i] = z4;
    for (int i = gt; i < V0; i += stride) g_scratch[OFF_XM + i] = x[i] * occ[i];
    for (int i = gt; i < V1; i += stride) {
        int xx = i % D1, yy = (i / D1) % D1, zz = i / (D1 * D1);
        float m = 0.f;
        #pragma unroll
        for (int dz = 0; dz < 2; dz++)
            #pragma unroll
            for (int dy = 0; dy < 2; dy++)
                #pragma unroll
                for (int dx = 0; dx < 2; dx++)
                    m = fmaxf(m, occ[((2 * zz + dz) * D0 + 2 * yy + dy) * D0 + 2 * xx + dx]);
        g_scratch[OFF_M1 + i] = m;
    }
    for (int i = gt; i < V2; i += stride) {
        int xx = i % D2, yy = (i / D2) % D2, zz = i / (D2 * D2);
        float m = 0.f;
        for (int dz = 0; dz < 4; dz++)
            for (int dy = 0; dy < 4; dy++)
                #pragma unroll
                for (int dx = 0; dx < 4; dx++)
                    m = fmaxf(m, occ[((4 * zz + dz) * D0 + 4 * yy + dy) * D0 + 4 * xx + dx]);
        g_scratch[OFF_M2 + i] = m;
    }
    if (gt == 0) { g_cnt[0] = 0; g_cnt[1] = 0; g_cnt[2] = 0; g_cnt[3] = 0; }
}

__global__ void lists_kernel(const float* __restrict__ occ) {
    const float* mask; int n; int* list; int* cnt;
    if (blockIdx.y == 0)      { mask = occ;                n = V0; list = g_list0; cnt = &g_cnt[0]; }
    else if (blockIdx.y == 1) { mask = g_scratch + OFF_M1; n = V1; list = g_list1; cnt = &g_cnt[1]; }
    else                      { mask = g_scratch + OFF_M2; n = V2; list = g_list2; cnt = &g_cnt[2]; }
    int lane = threadIdx.x & 31;
    for (int i = blockIdx.x * blockDim.x + threadIdx.x; i < n + 31;
         i += gridDim.x * blockDim.x) {
        bool pred = (i < n) && (mask[i] > 0.5f);
        unsigned bal = __ballot_sync(0xffffffffu, pred);
        int leader = __ffs(bal) - 1;
        int base = 0;
        if (bal && lane == leader) base = atomicAdd(cnt, __popc(bal));
        base = __shfl_sync(0xffffffffu, base, leader < 0 ? 0 : leader);
        if (pred) list[base + __popc(bal & ((1u << lane) - 1))] = i;
    }
}

struct WPtrs { const float* p[15]; };
__device__ const int TW_DIMS[15][4] = {
    {16, 1, 27, 16}, {32, 16, 8, 32}, {32, 32, 27, 32}, {32, 32, 27, 32},
    {64, 32, 8, 64}, {64, 64, 27, 64}, {64, 64, 27, 64}, {32, 64, 8, 32},
    {64, 64, 27, 64}, {32, 64, 27, 32}, {16, 32, 8, 16}, {32, 32, 27, 32},
    {16, 32, 27, 16}, {16, 16, 27, 16}, {5, 16, 27, 8}};
__device__ const int TW_OFF[15] = {
    WO_IN, WO_E0D, WO_E0A, WO_E0B, WO_E1D, WO_E1A, WO_E1B, WO_D0U,
    WO_D0A, WO_D0B, WO_D1U, WO_D1A, WO_D1B, WO_OA, WO_OB};

__global__ void tw_kernel(WPtrs wp) {
    int e = blockIdx.y;
    int Cout = TW_DIMS[e][0], Cin = TW_DIMS[e][1], K3 = TW_DIMS[e][2], Copad = TW_DIMS[e][3];
    const float* w = wp.p[e];
    float* wt = g_scratch + TW_OFF[e];
    int total = Cin * K3 * Copad;
    for (int i = blockIdx.x * blockDim.x + threadIdx.x; i < total;
         i += gridDim.x * blockDim.x) {
        int o = i % Copad;
        int r = i / Copad;
        int t = r / Cin, ci = r % Cin;
        wt[i] = (o < Cout) ? w[(o * Cin + ci) * K3 + t] : 0.f;
    }
}

// ---------------------------------------------------------------------------
// conv3 with smem weights + batched gathers.  CO_TILE = 4, TPV = OCG lanes/voxel.
// ---------------------------------------------------------------------------

template <int ICGA, int ICGB, int OCG, bool RELU>
__global__ __launch_bounds__(512)
void conv3_s(const float* __restrict__ inA, const float* __restrict__ inB,
             const float* __restrict__ wt, float* __restrict__ out,
             const int* __restrict__ list, const int* __restrict__ cnt,
             int cntIdx, int D) {
    constexpr int ICGT = ICGA + ICGB;
    constexpr int CIN = ICGT * 4;
    constexpr int COPAD = OCG * 4;
    constexpr int TPV = OCG;
    __shared__ float4 ws4[27 * COPAD];   // per tap: COPAD float4 = 4 ci rows x OCG

    const int vol = D * D * D;
    const int n = cnt[cntIdx];
    const long total = (long)n * TPV;
    const int stride = gridDim.x * blockDim.x;
    const int iters = (int)((total + stride - 1) / stride);
    const float4* wsrc = reinterpret_cast<const float4*>(wt);

    for (int it = 0; it < iters; it++) {
        long wbase = (long)it * stride + (long)blockIdx.x * blockDim.x;
        if (wbase >= total) continue;                 // whole block inactive (uniform)
        long w = wbase + threadIdx.x;
        bool active = w < total;
        int v = 0, co4 = 0;
        if (active) { v = list[w / TPV]; co4 = (int)(w % TPV); }
        int x0 = v % D, y0 = (v / D) % D, z0 = v / (D * D);
        bool xm0 = x0 >= 1, xm2 = x0 < D - 1;
        bool ym0 = y0 >= 1, ym2 = y0 < D - 1;
        float4 acc = make_float4(0.f, 0.f, 0.f, 0.f);

        #pragma unroll 1
        for (int g = 0; g < ICGT; g++) {
            __syncthreads();
            for (int i = threadIdx.x; i < 27 * COPAD; i += blockDim.x) {
                int t = i / COPAD;
                int k = i - t * COPAD;
                ws4[i] = wsrc[(t * CIN + 4 * g) * OCG + k];
            }
            __syncthreads();
            if (active) {
                const float* inP; int gl;
                if (g < ICGA) { inP = inA; gl = g; }
                else          { inP = inB; gl = g - ICGA; }
                const float* base = inP + (long)gl * vol * 4;
                #pragma unroll
                for (int p = 0; p < 3; p++) {
                    int zz = z0 + p - 1;
                    bool zok = (unsigned)zz < (unsigned)D;
                    int pb = (zz * D + y0) * D + x0;
                    float4 iv[9];
                    #pragma unroll
                    for (int q = 0; q < 9; q++) {
                        int dy = q / 3 - 1, dx = q % 3 - 1;
                        bool ok = zok
                            && (dy < 0 ? ym0 : (dy > 0 ? ym2 : true))
                            && (dx < 0 ? xm0 : (dx > 0 ? xm2 : true));
                        iv[q] = ok ? __ldg(reinterpret_cast<const float4*>(
                                         base + (long)(pb + dy * D + dx) * 4))
                                   : make_float4(0.f, 0.f, 0.f, 0.f);
                    }
                    #pragma unroll
                    for (int q = 0; q < 9; q++) {
                        int t = p * 9 + q;
                        const float4* wr = &ws4[t * COPAD + co4];
                        float fx[4] = {iv[q].x, iv[q].y, iv[q].z, iv[q].w};
                        #pragma unroll
                        for (int j = 0; j < 4; j++) {
                            float4 wv = wr[j * OCG];
                            acc.x += fx[j] * wv.x; acc.y += fx[j] * wv.y;
                            acc.z += fx[j] * wv.z; acc.w += fx[j] * wv.w;
                        }
                    }
                }
            }
        }
        if (active) {
            if (RELU) {
                acc.x = fmaxf(acc.x, 0.f); acc.y = fmaxf(acc.y, 0.f);
                acc.z = fmaxf(acc.z, 0.f); acc.w = fmaxf(acc.w, 0.f);
            }
            *reinterpret_cast<float4*>(out + ((long)co4 * vol + v) * 4) = acc;
        }
    }
}

// ---------------------------------------------------------------------------
// down2 / up2 (batched gathers, weights via L1)
// ---------------------------------------------------------------------------

template <int ICG, int OCG>
__global__ __launch_bounds__(256)
void down2_s(const float* __restrict__ in, const float* __restrict__ wt,
             float* __restrict__ out, const int* __restrict__ list,
             const int* __restrict__ cnt, int cntIdx, int Dc) {
    constexpr int CIN = ICG * 4;
    constexpr int COPAD = OCG * 4;
    constexpr int TPV = OCG;
    const int Df = Dc * 2;
    const int volf = Df * Df * Df;
    const int volc = Dc * Dc * Dc;
    const int n = cnt[cntIdx];
    const long total = (long)n * TPV;
    for (long w = (long)blockIdx.x * blockDim.x + threadIdx.x; w < total;
         w += (long)gridDim.x * blockDim.x) {
        int v = list[w / TPV];
        int co4 = (int)(w % TPV);
        int x0 = v % Dc, y0 = (v / Dc) % Dc, z0 = v / (Dc * Dc);
        int offs[8];
        #pragma unroll
        for (int t = 0; t < 8; t++) {
            int tz = t >> 2, ty = (t >> 1) & 1, tx = t & 1;
            offs[t] = ((2 * z0 + tz) * Df + 2 * y0 + ty) * Df + 2 * x0 + tx;
        }
        float4 acc = make_float4(0.f, 0.f, 0.f, 0.f);
        #pragma unroll 1
        for (int g = 0; g < ICG; g++) {
            float4 iv[8];
            #pragma unroll
            for (int t = 0; t < 8; t++)
                iv[t] = __ldg(reinterpret_cast<const float4*>(
                    in + ((long)g * volf + offs[t]) * 4));
            #pragma unroll
            for (int t = 0; t < 8; t++) {
                float fx[4] = {iv[t].x, iv[t].y, iv[t].z, iv[t].w};
                #pragma unroll
                for (int j = 0; j < 4; j++) {
                    float4 wv = __ldg(reinterpret_cast<const float4*>(
                        wt + ((long)(t * CIN + 4 * g + j) * COPAD) + co4 * 4));
                    acc.x += fx[j] * wv.x; acc.y += fx[j] * wv.y;
                    acc.z += fx[j] * wv.z; acc.w += fx[j] * wv.w;
                }
            }
        }
        *reinterpret_cast<float4*>(out + ((long)co4 * volc + v) * 4) = acc;
    }
}

template <int ICG, int OCG>
__global__ __launch_bounds__(256)
void up2_s(const float* __restrict__ in, const float* __restrict__ wt,
           float* __restrict__ out, const int* __restrict__ list,
           const int* __restrict__ cnt, int cntIdx, int Df) {
    constexpr int CIN = ICG * 4;
    constexpr int COPAD = OCG * 4;
    constexpr int TPV = OCG;
    const int Dc = Df / 2;
    const int volf = Df * Df * Df;
    const int volc = Dc * Dc * Dc;
    const int n = cnt[cntIdx];
    const long total = (long)n * TPV;
    for (long w = (long)blockIdx.x * blockDim.x + threadIdx.x; w < total;
         w += (long)gridDim.x * blockDim.x) {
        int v = list[w / TPV];
        int co4 = (int)(w % TPV);
        int x0 = v % Df, y0 = (v / Df) % Df, z0 = v / (Df * Df);
        int t = ((1 - (z0 & 1)) * 2 + (1 - (y0 & 1))) * 2 + (1 - (x0 & 1));
        int coff = ((z0 >> 1) * Dc + (y0 >> 1)) * Dc + (x0 >> 1);
        float4 acc = make_float4(0.f, 0.f, 0.f, 0.f);
        #pragma unroll 1
        for (int g = 0; g < ICG; g++) {
            float4 iv = __ldg(reinterpret_cast<const float4*>(
                in + ((long)g * volc + coff) * 4));
            float fx[4] = {iv.x, iv.y, iv.z, iv.w};
            #pragma unroll
            for (int j = 0; j < 4; j++) {
                float4 wv = __ldg(reinterpret_cast<const float4*>(
                    wt + ((long)(t * CIN + 4 * g + j) * COPAD) + co4 * 4));
                acc.x += fx[j] * wv.x; acc.y += fx[j] * wv.y;
                acc.z += fx[j] * wv.z; acc.w += fx[j] * wv.w;
            }
        }
        *reinterpret_cast<float4*>(out + ((long)co4 * volf + v) * 4) = acc;
    }
}

// ---------------------------------------------------------------------------
// input conv (1->16) and output conv (16->5)
// ---------------------------------------------------------------------------

__global__ __launch_bounds__(256)
void conv_in_s(const float* __restrict__ xm, const float* __restrict__ wt,
               float* __restrict__ out, const int* __restrict__ list,
               const int* __restrict__ cnt) {
    const int D = D0, vol = V0;
    int n = cnt[0];
    for (int w = blockIdx.x * blockDim.x + threadIdx.x; w < n;
         w += gridDim.x * blockDim.x) {
        int v = list[w];
        int x0 = v % D, y0 = (v / D) % D, z0 = v / (D * D);
        bool xm0 = x0 >= 1, xm2 = x0 < D - 1;
        bool ym0 = y0 >= 1, ym2 = y0 < D - 1;
        float acc[16];
        #pragma unroll
        for (int k = 0; k < 16; k++) acc[k] = 0.f;
        #pragma unroll
        for (int p = 0; p < 3; p++) {
            int zz = z0 + p - 1;
            bool zok = (unsigned)zz < (unsigned)D;
            int pb = (zz * D + y0) * D + x0;
            float iv[9];
            #pragma unroll
            for (int q = 0; q < 9; q++) {
                int dy = q / 3 - 1, dx = q % 3 - 1;
                bool ok = zok
                    && (dy < 0 ? ym0 : (dy > 0 ? ym2 : true))
                    && (dx < 0 ? xm0 : (dx > 0 ? xm2 : true));
                iv[q] = ok ? __ldg(xm + pb + dy * D + dx) : 0.f;
            }
            #pragma unroll
            for (int q = 0; q < 9; q++) {
                const float* wp = wt + (p * 9 + q) * 16;
                #pragma unroll
                for (int c = 0; c < 16; c += 4) {
                    float4 wv = __ldg(reinterpret_cast<const float4*>(wp + c));
                    acc[c + 0] += iv[q] * wv.x; acc[c + 1] += iv[q] * wv.y;
                    acc[c + 2] += iv[q] * wv.z; acc[c + 3] += iv[q] * wv.w;
                }
            }
        }
        #pragma unroll
        for (int k = 0; k < 16; k += 4)
            *reinterpret_cast<float4*>(out + ((long)(k / 4) * vol + v) * 4) =
                make_float4(acc[k], acc[k + 1], acc[k + 2], acc[k + 3]);
    }
}

__global__ __launch_bounds__(256)
void conv_out_s(const float* __restrict__ in, const float* __restrict__ wt,
                float* __restrict__ out, const int* __restrict__ list,
                const int* __restrict__ cnt) {
    const int D = D0, vol = V0;
    int n = cnt[0];
    for (int w = blockIdx.x * blockDim.x + threadIdx.x; w < n;
         w += gridDim.x * blockDim.x) {
        int v = list[w];
        int x0 = v % D, y0 = (v / D) % D, z0 = v / (D * D);
        bool xm0 = x0 >= 1, xm2 = x0 < D - 1;
        bool ym0 = y0 >= 1, ym2 = y0 < D - 1;
        float acc[8];
        #pragma unroll
        for (int k = 0; k < 8; k++) acc[k] = 0.f;
        #pragma unroll 1
        for (int g = 0; g < 4; g++) {
            #pragma unroll
            for (int p = 0; p < 3; p++) {
                int zz = z0 + p - 1;
                bool zok = (unsigned)zz < (unsigned)D;
                int pb = (zz * D + y0) * D + x0;
                float4 iv[9];
                #pragma unroll
                for (int q = 0; q < 9; q++) {
                    int dy = q / 3 - 1, dx = q % 3 - 1;
                    bool ok = zok
                        && (dy < 0 ? ym0 : (dy > 0 ? ym2 : true))
                        && (dx < 0 ? xm0 : (dx > 0 ? xm2 : true));
                    iv[q] = ok ? __ldg(reinterpret_cast<const float4*>(
                                     in + ((long)g * vol + pb + dy * D + dx) * 4))
                               : make_float4(0.f, 0.f, 0.f, 0.f);
                }
                #pragma unroll
                for (int q = 0; q < 9; q++) {
                    int t = p * 9 + q;
                    float fx[4] = {iv[q].x, iv[q].y, iv[q].z, iv[q].w};
                    #pragma unroll
                    for (int j = 0; j < 4; j++) {
                        const float* wp = wt + (long)(t * 16 + 4 * g + j) * 8;
                        float4 w0 = __ldg(reinterpret_cast<const float4*>(wp));
                        float4 w1 = __ldg(reinterpret_cast<const float4*>(wp + 4));
                        acc[0] += fx[j] * w0.x; acc[1] += fx[j] * w0.y;
                        acc[2] += fx[j] * w0.z; acc[3] += fx[j] * w0.w;
                        acc[4] += fx[j] * w1.x; acc[5] += fx[j] * w1.y;
                        acc[6] += fx[j] * w1.z; acc[7] += fx[j] * w1.w;
                    }
                }
            }
        }
        #pragma unroll
        for (int c = 0; c < 5; c++) out[(long)c * vol + v] = acc[c];
    }
}

// ---------------------------------------------------------------------------
// launch
// ---------------------------------------------------------------------------

extern "C" void kernel_launch(void* const* d_in, const int* in_sizes, int n_in,
                              void* d_out, int out_size) {
    (void)in_sizes; (void)n_in;
    const float* x   = (const float*)d_in[0];
    const float* occ = (const float*)d_in[1];
    float* out = (float*)d_out;

    float* SB = nullptr;
    int *L0 = nullptr, *L1 = nullptr, *L2 = nullptr, *CNT = nullptr;
    cudaGetSymbolAddress((void**)&SB,  g_scratch);
    cudaGetSymbolAddress((void**)&L0,  g_list0);
    cudaGetSymbolAddress((void**)&L1,  g_list1);
    cudaGetSymbolAddress((void**)&L2,  g_list2);
    cudaGetSymbolAddress((void**)&CNT, g_cnt);

    prep1_kernel<<<1024, 256>>>(x, occ, out, out_size);
    lists_kernel<<<dim3(432, 3), 256>>>(occ);
    WPtrs wp;
    for (int i = 0; i < 15; i++) wp.p[i] = (const float*)d_in[2 + i];
    tw_kernel<<<dim3(216, 15), 256>>>(wp);

    const int CB = 1440;   // conv3_s blocks (512 threads)

    // input conv 1->16 @96
    conv_in_s<<<1024, 256>>>(SB + OFF_XM, SB + WO_IN, SB + OFF_SKIP0, L0, CNT);

    // encoder level 0
    down2_s<4, 8><<<2048, 256>>>(SB + OFF_SKIP0, SB + WO_E0D, SB + OFF_HA, L1, CNT, 1, D1);
    conv3_s<8, 0, 8, true><<<CB, 512>>>(SB + OFF_HA, nullptr, SB + WO_E0A, SB + OFF_HB, L1, CNT, 1, D1);
    conv3_s<8, 0, 8, false><<<CB, 512>>>(SB + OFF_HB, nullptr, SB + WO_E0B, SB + OFF_S1, L1, CNT, 1, D1);

    // encoder level 1
    down2_s<8, 16><<<864, 256>>>(SB + OFF_S1, SB + WO_E1D, SB + OFF_CA, L2, CNT, 2, D2);
    conv3_s<16, 0, 16, true><<<432, 512>>>(SB + OFF_CA, nullptr, SB + WO_E1A, SB + OFF_CB, L2, CNT, 2, D2);
    conv3_s<16, 0, 16, false><<<432, 512>>>(SB + OFF_CB, nullptr, SB + WO_E1B, SB + OFF_CA, L2, CNT, 2, D2);

    // decoder stage 0 (to level 1)
    up2_s<16, 8><<<2048, 256>>>(SB + OFF_CA, SB + WO_D0U, SB + OFF_HA, L1, CNT, 1, D1);
    conv3_s<8, 8, 16, true><<<CB, 512>>>(SB + OFF_HA, SB + OFF_S1, SB + WO_D0A, SB + OFF_H64, L1, CNT, 1, D1);
    conv3_s<16, 0, 8, false><<<CB, 512>>>(SB + OFF_H64, nullptr, SB + WO_D0B, SB + OFF_HB, L1, CNT, 1, D1);

    // decoder stage 1 (to level 0)
    up2_s<8, 4><<<2048, 256>>>(SB + OFF_HB, SB + WO_D1U, SB + OFF_UP1, L0, CNT, 0, D0);
    conv3_s<4, 4, 8, true><<<CB, 512>>>(SB + OFF_UP1, SB + OFF_SKIP0, SB + WO_D1A, SB + OFF_T32, L0, CNT, 0, D0);
    conv3_s<8, 0, 4, false><<<CB, 512>>>(SB + OFF_T32, nullptr, SB + WO_D1B, SB + OFF_UP1, L0, CNT, 0, D0);

    // output block
    conv3_s<4, 0, 4, true><<<CB, 512>>>(SB + OFF_UP1, nullptr, SB + WO_OA, SB + OFF_SKIP0, L0, CNT, 0, D0);
    conv_out_s<<<1024, 256>>>(SB + OFF_SKIP0, SB + WO_OB, out, L0, CNT);
}